// round 15
// baseline (speedup 1.0000x reference)
#include <cuda_runtime.h>
#include <cuda_fp16.h>
#include <math.h>
#include <stdint.h>

#define B 32
#define N 32768
#define D 128
#define CH 128
#define NCH (N / CH)       // 256

#define NT 256
#define PITCH 136          // halves per fp16 tile row (272 B, 16B-aligned)
#define PITCHF 132         // floats per staging row

// smem byte offsets (k_chunk) — ES aliases XT (XT dead after GEMM1)
#define SM_YH 0            // [128][PITCH] fp16  34816 B
#define SM_YL 34816
#define SM_XT 69632        // [64][PITCH] fp16   17408 B
#define SM_ES 69632        // alias of XT
#define SM_Y2 87040        // float[128]
#define SM_SA 87552        // float[32]
#define SM_SC 87680
#define SM_RED 87808       // float[8][32]
#define SM_CM 88832        // float[32]
#define SM_SSC 88960
#define SM_X2 89088
#define SM_VAR 89216
#define SMEM_TOTAL 89344   // x2 = 178.7 KB <= 228 KB: 2 CTAs/SM
#define SM_PS 0            // f32 [64][PITCHF] staging, aliases Y tiles after GEMM2

#define L2E 1.44269504f

// gmem scratch (no allocations allowed)
__device__ float g_cmax[B * NCH];
__device__ float g_csum[B * NCH];
__device__ float g_cvec[NCH * B * D];      // [c][b][d]

__device__ __forceinline__ uint32_t s2u(const void* p) {
    uint32_t a;
    asm("{ .reg .u64 t; cvta.to.shared.u64 t, %1; cvt.u32.u64 %0, t; }" : "=r"(a) : "l"(p));
    return a;
}
__device__ __forceinline__ float ex2f(float x) {
    float y; asm("ex2.approx.f32 %0, %1;" : "=f"(y) : "f"(x)); return y;
}
__device__ __forceinline__ void ldsm4(uint32_t a, uint32_t r[4]) {
    asm volatile("ldmatrix.sync.aligned.m8n8.x4.shared.b16 {%0,%1,%2,%3}, [%4];"
        : "=r"(r[0]), "=r"(r[1]), "=r"(r[2]), "=r"(r[3]) : "r"(a));
}
__device__ __forceinline__ void ldsm2(uint32_t a, uint32_t r[2]) {
    asm volatile("ldmatrix.sync.aligned.m8n8.x2.shared.b16 {%0,%1}, [%2];"
        : "=r"(r[0]), "=r"(r[1]) : "r"(a));
}
__device__ __forceinline__ void ldsm2t(uint32_t a, uint32_t r[2]) {
    asm volatile("ldmatrix.sync.aligned.m8n8.x2.trans.shared.b16 {%0,%1}, [%2];"
        : "=r"(r[0]), "=r"(r[1]) : "r"(a));
}
__device__ __forceinline__ void mma16816(float c[4], const uint32_t a[4], const uint32_t b[2]) {
    asm volatile("mma.sync.aligned.m16n8k16.row.col.f32.f16.f16.f32 "
        "{%0,%1,%2,%3}, {%4,%5,%6,%7}, {%8,%9}, {%0,%1,%2,%3};"
        : "+f"(c[0]), "+f"(c[1]), "+f"(c[2]), "+f"(c[3])
        : "r"(a[0]), "r"(a[1]), "r"(a[2]), "r"(a[3]), "r"(b[0]), "r"(b[1]));
}

// ---------------------------------------------------------------------------
// K1: HMMA chunk kernel. Grid NCH = 256, 256 threads, 2 CTAs/SM.
// ---------------------------------------------------------------------------
__global__ __launch_bounds__(NT, 2) void k_chunk(const float* __restrict__ x,
                                                 const float* __restrict__ al,
                                                 const float* __restrict__ y) {
    extern __shared__ char smem[];
    const uint32_t sb = s2u(smem);
    const int t = threadIdx.x, w = t >> 5, lane = t & 31;
    const int c = blockIdx.x;

    if (t < B) {
        float a = al[t], var = 1.0f - a;
        *(float*)(smem + SM_VAR + t * 4) = var;
        *(float*)(smem + SM_SSC + t * 4) = sqrtf(a) / var;
        *(float*)(smem + SM_SC + t * 4) = 0.5f * a / var;
    }
    __syncthreads();

    // build x~ tile in smem + x2 partials (8 threads per b, 16 k each)
    {
        const int b = t >> 3, kb = (t & 7) * 16;
        const float sc_ = *(const float*)(smem + SM_SSC + b * 4);
        float x2p = 0.f;
        #pragma unroll
        for (int j = 0; j < 16; j++) {
            const int k = kb + j;
            float raw = x[b * D + k];
            x2p = fmaf(raw, raw, x2p);
            float xv = sc_ * raw;
            __half h = __float2half_rn(xv);
            __half lo = __float2half_rn(xv - __half2float(h));
            *(__half*)(smem + SM_XT + ((uint32_t)b * PITCH + k) * 2) = h;
            *(__half*)(smem + SM_XT + ((uint32_t)(b + 32) * PITCH + k) * 2) = lo;
        }
        x2p += __shfl_xor_sync(0xffffffffu, x2p, 1);
        x2p += __shfl_xor_sync(0xffffffffu, x2p, 2);
        x2p += __shfl_xor_sync(0xffffffffu, x2p, 4);
        if ((t & 7) == 0) *(float*)(smem + SM_X2 + b * 4) = x2p;
    }

    // stage y: fp32 -> yh/yl fp16 tiles + y2 per row
    {
        const float4* y4 = (const float4*)(y + (size_t)c * CH * D);
        #pragma unroll
        for (int kk = 0; kk < 16; kk++) {
            const int i = kk * NT + t;
            const int row = i >> 5;
            const int c4 = (i & 31) * 4;
            float4 v = y4[i];
            float sq = fmaf(v.x, v.x, fmaf(v.y, v.y, fmaf(v.z, v.z, v.w * v.w)));
            #pragma unroll
            for (int o = 16; o > 0; o >>= 1) sq += __shfl_xor_sync(0xffffffffu, sq, o);
            if (lane == 0) *(float*)(smem + SM_Y2 + row * 4) = sq;
            __half hx = __float2half_rn(v.x), hy = __float2half_rn(v.y);
            __half hz = __float2half_rn(v.z), hw = __float2half_rn(v.w);
            __half2 h01 = __halves2half2(hx, hy), h23 = __halves2half2(hz, hw);
            __half2 l01 = __halves2half2(__float2half_rn(v.x - __half2float(hx)),
                                         __float2half_rn(v.y - __half2float(hy)));
            __half2 l23 = __halves2half2(__float2half_rn(v.z - __half2float(hz)),
                                         __float2half_rn(v.w - __half2float(hw)));
            const uint32_t off = (uint32_t)(row * PITCH + c4) * 2;
            *(__half2*)(smem + SM_YH + off) = h01;
            *(__half2*)(smem + SM_YH + off + 4) = h23;
            *(__half2*)(smem + SM_YL + off) = l01;
            *(__half2*)(smem + SM_YL + off + 4) = l23;
        }
    }
    __syncthreads();

    if (t < B) {
        float var = *(const float*)(smem + SM_VAR + t * 4);
        float x2 = *(const float*)(smem + SM_X2 + t * 4);
        *(float*)(smem + SM_SA + t * 4) = -(0.5f * (float)D * logf(var) + 0.5f / var * x2);
    }
    __syncthreads();

    // ---- GEMM1: L[n=128, bp=64] = (Yh+Yl) * XT^T ----
    float acc[8][4];
    #pragma unroll
    for (int j = 0; j < 8; j++)
        #pragma unroll
        for (int q = 0; q < 4; q++) acc[j][q] = 0.f;

    const int nb = w * 16;
    const uint32_t aAddr = sb + SM_YH + (uint32_t)(nb + (lane & 15)) * (PITCH * 2)
                         + (uint32_t)(((lane >> 4) << 3) * 2);
    const uint32_t bAddr = sb + SM_XT + (uint32_t)(lane & 7) * (PITCH * 2)
                         + (uint32_t)((((lane >> 3) & 1) << 3) * 2);
    #pragma unroll
    for (int ks = 0; ks < 8; ks++) {
        const uint32_t kOff = (uint32_t)(ks * 32);
        uint32_t ah[4], alr[4];
        ldsm4(aAddr + kOff, ah);
        ldsm4(aAddr + (SM_YL - SM_YH) + kOff, alr);
        #pragma unroll
        for (int j = 0; j < 8; j++) {
            uint32_t bb[2];
            ldsm2(bAddr + (uint32_t)(j * 8) * (PITCH * 2) + kOff, bb);
            mma16816(acc[j], ah, bb);
            mma16816(acc[j], alr, bb);
        }
    }

    // ---- epilogue 1 ----
    const int n0 = nb + (lane >> 2);
    const float y20 = *(const float*)(smem + SM_Y2 + n0 * 4);
    const float y21 = *(const float*)(smem + SM_Y2 + (n0 + 8) * 4);
    const float* sAs = (const float*)(smem + SM_SA);
    const float* sCs = (const float*)(smem + SM_SC);
    float* red = (float*)(smem + SM_RED);
    float* cmv = (float*)(smem + SM_CM);

    float lv[4][4];
    float mx[4][2];
    #pragma unroll
    for (int j = 0; j < 4; j++) {
        #pragma unroll
        for (int cc = 0; cc < 2; cc++) {
            const int b2 = j * 8 + 2 * (lane & 3) + cc;
            lv[j][cc]     = acc[j][cc]     + acc[j + 4][cc]     + sAs[b2] - sCs[b2] * y20;
            lv[j][cc + 2] = acc[j][cc + 2] + acc[j + 4][cc + 2] + sAs[b2] - sCs[b2] * y21;
            float m = fmaxf(lv[j][cc], lv[j][cc + 2]);
            #pragma unroll
            for (int o = 4; o < 32; o <<= 1) m = fmaxf(m, __shfl_xor_sync(0xffffffffu, m, o));
            mx[j][cc] = m;
        }
    }
    if (lane < 4) {
        #pragma unroll
        for (int j = 0; j < 4; j++)
            #pragma unroll
            for (int cc = 0; cc < 2; cc++)
                red[w * 32 + j * 8 + 2 * lane + cc] = mx[j][cc];
    }
    __syncthreads();       // also: all warps done with XT -> ES alias safe
    if (t < 32) {
        float m = -3.4e38f;
        #pragma unroll
        for (int w2 = 0; w2 < 8; w2++) m = fmaxf(m, red[w2 * 32 + t]);
        cmv[t] = m;
        g_cmax[t * NCH + c] = m;
    }
    __syncthreads();

    float sv[4][2];
    #pragma unroll
    for (int j = 0; j < 4; j++) {
        #pragma unroll
        for (int cc = 0; cc < 2; cc++) {
            const int b2 = j * 8 + 2 * (lane & 3) + cc;
            const float cmb = cmv[b2];
            float e0 = ex2f((lv[j][cc] - cmb) * L2E);
            float e1 = ex2f((lv[j][cc + 2] - cmb) * L2E);
            __half h0 = __float2half_rn(e0), h1 = __float2half_rn(e1);
            __half l0 = __float2half_rn(e0 - __half2float(h0));
            __half l1 = __float2half_rn(e1 - __half2float(h1));
            *(__half*)(smem + SM_ES + ((uint32_t)b2 * PITCH + n0) * 2) = h0;
            *(__half*)(smem + SM_ES + ((uint32_t)b2 * PITCH + n0 + 8) * 2) = h1;
            *(__half*)(smem + SM_ES + ((uint32_t)(b2 + 32) * PITCH + n0) * 2) = l0;
            *(__half*)(smem + SM_ES + ((uint32_t)(b2 + 32) * PITCH + n0 + 8) * 2) = l1;
            float s = e0 + e1;
            #pragma unroll
            for (int o = 4; o < 32; o <<= 1) s += __shfl_xor_sync(0xffffffffu, s, o);
            sv[j][cc] = s;
        }
    }
    if (lane < 4) {
        #pragma unroll
        for (int j = 0; j < 4; j++)
            #pragma unroll
            for (int cc = 0; cc < 2; cc++)
                red[w * 32 + j * 8 + 2 * lane + cc] = sv[j][cc];
    }
    __syncthreads();
    if (t < 32) {
        float s = 0.f;
        #pragma unroll
        for (int w2 = 0; w2 < 8; w2++) s += red[w2 * 32 + t];
        g_csum[t * NCH + c] = s;
    }

    // ---- GEMM2: V[bp=64, d=128] = ES * (Yh+Yl) ----
    float a2[8][4];
    #pragma unroll
    for (int j = 0; j < 8; j++)
        #pragma unroll
        for (int q = 0; q < 4; q++) a2[j][q] = 0.f;

    const int mb = (w & 3) * 16;
    const int db = (w >> 2) * 64;
    const uint32_t aeAddr = sb + SM_ES + (uint32_t)(mb + (lane & 15)) * (PITCH * 2)
                          + (uint32_t)(((lane >> 4) << 3) * 2);
    const uint32_t btRow = (uint32_t)(lane & 15) * (PITCH * 2);
    #pragma unroll
    for (int ks = 0; ks < 8; ks++) {
        const uint32_t nOff = (uint32_t)(ks * 16);
        uint32_t ae[4];
        ldsm4(aeAddr + nOff * 2, ae);
        const uint32_t ybase = nOff * (PITCH * 2) + btRow;
        #pragma unroll
        for (int j = 0; j < 8; j++) {
            const uint32_t dOff = (uint32_t)(db + j * 8) * 2;
            uint32_t bh[2], bl[2];
            ldsm2t(sb + SM_YH + ybase + dOff, bh);
            ldsm2t(sb + SM_YL + ybase + dOff, bl);
            mma16816(a2[j], ae, bh);
            mma16816(a2[j], ae, bl);
        }
    }
    __syncthreads();

    const int r0 = mb + (lane >> 2);
    #pragma unroll
    for (int j = 0; j < 8; j++) {
        const int dc = db + j * 8 + 2 * (lane & 3);
        *(float2*)(smem + SM_PS + ((uint32_t)r0 * PITCHF + dc) * 4) =
            make_float2(a2[j][0], a2[j][1]);
        *(float2*)(smem + SM_PS + ((uint32_t)(r0 + 8) * PITCHF + dc) * 4) =
            make_float2(a2[j][2], a2[j][3]);
    }
    __syncthreads();

    #pragma unroll
    for (int i4 = t; i4 < 1024; i4 += NT) {
        const int b2 = i4 >> 5, d4 = (i4 & 31) * 4;
        float4 pa = *(const float4*)(smem + SM_PS + ((uint32_t)b2 * PITCHF + d4) * 4);
        float4 pb = *(const float4*)(smem + SM_PS + ((uint32_t)(b2 + 32) * PITCHF + d4) * 4);
        float4 o = make_float4(pa.x + pb.x, pa.y + pb.y, pa.z + pb.z, pa.w + pb.w);
        *(float4*)(g_cvec + ((size_t)c * B + b2) * D + d4) = o;
    }
}

// ---------------------------------------------------------------------------
// K2: finisher. Grid = B*4 = 128 CTAs, 256 threads.
//  CTA (b, dg): redundant M_b/SE_b; warp w reduces chunks [32w, 32w+32)
//  for d = dg*32 + lane with explicit 8-deep load batching (MLP>=8).
// ---------------------------------------------------------------------------
__global__ __launch_bounds__(256) void k_final(const float* __restrict__ x,
                                               const float* __restrict__ al,
                                               float* __restrict__ out) {
    __shared__ float sc[NCH];
    __shared__ float red[8];
    __shared__ float ps[8][32];
    __shared__ float sM, sSE;
    const int t = threadIdx.x, lane = t & 31, w = t >> 5;
    const int b = blockIdx.x >> 2;
    const int dg = blockIdx.x & 3;

    const float cm0 = g_cmax[b * NCH + t];
    {
        float m = cm0;
        #pragma unroll
        for (int o = 16; o > 0; o >>= 1) m = fmaxf(m, __shfl_xor_sync(0xffffffffu, m, o));
        if (lane == 0) red[w] = m;
    }
    __syncthreads();
    if (t == 0) {
        float m = red[0];
        #pragma unroll
        for (int i = 1; i < 8; i++) m = fmaxf(m, red[i]);
        sM = m;
    }
    __syncthreads();
    {
        float s = __expf(cm0 - sM);
        sc[t] = s;
        float p = s * g_csum[b * NCH + t];
        #pragma unroll
        for (int o = 16; o > 0; o >>= 1) p += __shfl_xor_sync(0xffffffffu, p, o);
        if (lane == 0) red[w] = p;
    }
    __syncthreads();
    if (t == 0) {
        float s = 0.f;
        #pragma unroll
        for (int i = 0; i < 8; i++) s += red[i];
        sSE = s;
    }
    __syncthreads();

    // v reduction with explicit load batching
    const int d = dg * 32 + lane;
    const float* base = g_cvec + (size_t)b * D + d;
    float v = 0.f;
    #pragma unroll
    for (int jo = 0; jo < 4; jo++) {
        float tmp[8], scv[8];
        #pragma unroll
        for (int ji = 0; ji < 8; ji++) {
            const int cc = w * 32 + jo * 8 + ji;
            tmp[ji] = base[(size_t)cc * B * D];
            scv[ji] = sc[cc];
        }
        #pragma unroll
        for (int ji = 0; ji < 8; ji++) v = fmaf(scv[ji], tmp[ji], v);
    }
    ps[w][lane] = v;
    __syncthreads();

    if (t < 32) {
        float vv = 0.f;
        #pragma unroll
        for (int w2 = 0; w2 < 8; w2++) vv += ps[w2][t];
        const int dd = dg * 32 + t;
        float a = al[b];
        float var = 1.f - a;
        out[b * D + dd] = (x[b * D + dd] - sqrtf(a) * (vv / sSE)) * rsqrtf(var);
    }
}

extern "C" void kernel_launch(void* const* d_in, const int* in_sizes, int n_in,
                              void* d_out, int out_size) {
    const float* x  = (const float*)d_in[0];
    const float* al = (const float*)d_in[1];
    const float* y  = (const float*)d_in[2];
    float* out = (float*)d_out;

    cudaFuncSetAttribute(k_chunk, cudaFuncAttributeMaxDynamicSharedMemorySize, SMEM_TOTAL);

    k_chunk<<<NCH, NT, SMEM_TOTAL>>>(x, al, y);
    k_final<<<B * 4, 256>>>(x, al, out);
}

// round 16
// speedup vs baseline: 1.0122x; 1.0122x over previous
#include <cuda_runtime.h>
#include <cuda_fp16.h>
#include <math.h>
#include <stdint.h>

#define B 32
#define N 32768
#define D 128
#define CH 256             // n per chunk (2 subtiles of 128)
#define NCH (N / CH)       // 128 chunks
#define NSUB 2

#define NT 256
#define PITCH 136          // halves per fp16 tile row (272 B, 16B-aligned)
#define PITCHF 132         // floats per staging row

// smem byte offsets (k_chunk) — ES separate (XT lives across subtiles)
#define SM_YH 0            // [128][PITCH] fp16  34816 B
#define SM_YL 34816
#define SM_XT 69632        // [64][PITCH] fp16   17408 B
#define SM_ES 87040        // [64][PITCH] fp16   17408 B
#define SM_Y2 104448       // float[128]
#define SM_SA 104960       // float[32]
#define SM_SC 105088
#define SM_RED 105216      // float[8][32]
#define SM_CM 106240       // float[32]  running max
#define SM_SSC 106368
#define SM_X2 106496
#define SM_VAR 106624
#define SM_SFO 106752      // float[32]  rescale factor exp(m_old-m_new)
#define SM_SRUN 106880     // float[32]  running sum
#define SMEM_TOTAL 107008
#define SM_PS 0            // f32 [64][PITCHF] staging, aliases Y tiles at the end

#define L2E 1.44269504f

// gmem scratch (no allocations allowed)
__device__ float g_cmax[B * NCH];
__device__ float g_csum[B * NCH];
__device__ float g_cvec[NCH * B * D];      // [c][b][d], 2 MB

__device__ __forceinline__ uint32_t s2u(const void* p) {
    uint32_t a;
    asm("{ .reg .u64 t; cvta.to.shared.u64 t, %1; cvt.u32.u64 %0, t; }" : "=r"(a) : "l"(p));
    return a;
}
__device__ __forceinline__ float ex2f(float x) {
    float y; asm("ex2.approx.f32 %0, %1;" : "=f"(y) : "f"(x)); return y;
}
__device__ __forceinline__ void ldsm4(uint32_t a, uint32_t r[4]) {
    asm volatile("ldmatrix.sync.aligned.m8n8.x4.shared.b16 {%0,%1,%2,%3}, [%4];"
        : "=r"(r[0]), "=r"(r[1]), "=r"(r[2]), "=r"(r[3]) : "r"(a));
}
__device__ __forceinline__ void ldsm2(uint32_t a, uint32_t r[2]) {
    asm volatile("ldmatrix.sync.aligned.m8n8.x2.shared.b16 {%0,%1}, [%2];"
        : "=r"(r[0]), "=r"(r[1]) : "r"(a));
}
__device__ __forceinline__ void ldsm2t(uint32_t a, uint32_t r[2]) {
    asm volatile("ldmatrix.sync.aligned.m8n8.x2.trans.shared.b16 {%0,%1}, [%2];"
        : "=r"(r[0]), "=r"(r[1]) : "r"(a));
}
__device__ __forceinline__ void mma16816(float c[4], const uint32_t a[4], const uint32_t b[2]) {
    asm volatile("mma.sync.aligned.m16n8k16.row.col.f32.f16.f16.f32 "
        "{%0,%1,%2,%3}, {%4,%5,%6,%7}, {%8,%9}, {%0,%1,%2,%3};"
        : "+f"(c[0]), "+f"(c[1]), "+f"(c[2]), "+f"(c[3])
        : "r"(a[0]), "r"(a[1]), "r"(a[2]), "r"(a[3]), "r"(b[0]), "r"(b[1]));
}

// ---------------------------------------------------------------------------
// K1: HMMA chunk kernel, 2 subtiles with online softmax. Grid 128, 256 thr.
// ---------------------------------------------------------------------------
__global__ __launch_bounds__(NT) void k_chunk(const float* __restrict__ x,
                                              const float* __restrict__ al,
                                              const float* __restrict__ y) {
    extern __shared__ char smem[];
    const uint32_t sb = s2u(smem);
    const int t = threadIdx.x, w = t >> 5, lane = t & 31;
    const int c = blockIdx.x;

    if (t < B) {
        float a = al[t], var = 1.0f - a;
        *(float*)(smem + SM_VAR + t * 4) = var;
        *(float*)(smem + SM_SSC + t * 4) = sqrtf(a) / var;
        *(float*)(smem + SM_SC + t * 4) = 0.5f * a / var;
        *(float*)(smem + SM_CM + t * 4) = -3.4e38f;
        *(float*)(smem + SM_SRUN + t * 4) = 0.f;
    }
    __syncthreads();

    // x~ tile + x2 partials (8 threads per b, 16 k each)
    {
        const int b = t >> 3, kb = (t & 7) * 16;
        const float sc_ = *(const float*)(smem + SM_SSC + b * 4);
        float x2p = 0.f;
        #pragma unroll
        for (int j = 0; j < 16; j++) {
            const int k = kb + j;
            float raw = x[b * D + k];
            x2p = fmaf(raw, raw, x2p);
            float xv = sc_ * raw;
            __half h = __float2half_rn(xv);
            __half lo = __float2half_rn(xv - __half2float(h));
            *(__half*)(smem + SM_XT + ((uint32_t)b * PITCH + k) * 2) = h;
            *(__half*)(smem + SM_XT + ((uint32_t)(b + 32) * PITCH + k) * 2) = lo;
        }
        x2p += __shfl_xor_sync(0xffffffffu, x2p, 1);
        x2p += __shfl_xor_sync(0xffffffffu, x2p, 2);
        x2p += __shfl_xor_sync(0xffffffffu, x2p, 4);
        if ((t & 7) == 0) *(float*)(smem + SM_X2 + b * 4) = x2p;
    }
    __syncthreads();
    if (t < B) {
        float var = *(const float*)(smem + SM_VAR + t * 4);
        float x2 = *(const float*)(smem + SM_X2 + t * 4);
        *(float*)(smem + SM_SA + t * 4) = -(0.5f * (float)D * logf(var) + 0.5f / var * x2);
    }

    // persistent GEMM2 accumulators (online-rescaled across subtiles)
    float a2[8][4];
    #pragma unroll
    for (int j = 0; j < 8; j++)
        #pragma unroll
        for (int q = 0; q < 4; q++) a2[j][q] = 0.f;

    const int nb = w * 16;
    const int mb = (w & 3) * 16;
    const int db = (w >> 2) * 64;
    const int r0 = mb + (lane >> 2);
    float* red = (float*)(smem + SM_RED);
    float* cmv = (float*)(smem + SM_CM);
    float* sfo = (float*)(smem + SM_SFO);
    float* srun = (float*)(smem + SM_SRUN);

    #pragma unroll 1
    for (int s = 0; s < NSUB; s++) {
        __syncthreads();   // Y/ES safe to (re)write; sA ready (s=0)

        // stage y subtile: fp32 -> yh/yl fp16 tiles + y2 per row
        {
            const float4* y4 = (const float4*)(y + ((size_t)c * NSUB + s) * 128 * D);
            #pragma unroll
            for (int kk = 0; kk < 16; kk++) {
                const int i = kk * NT + t;
                const int row = i >> 5;
                const int c4 = (i & 31) * 4;
                float4 v = y4[i];
                float sq = fmaf(v.x, v.x, fmaf(v.y, v.y, fmaf(v.z, v.z, v.w * v.w)));
                #pragma unroll
                for (int o = 16; o > 0; o >>= 1) sq += __shfl_xor_sync(0xffffffffu, sq, o);
                if (lane == 0) *(float*)(smem + SM_Y2 + row * 4) = sq;
                __half hx = __float2half_rn(v.x), hy = __float2half_rn(v.y);
                __half hz = __float2half_rn(v.z), hw = __float2half_rn(v.w);
                __half2 h01 = __halves2half2(hx, hy), h23 = __halves2half2(hz, hw);
                __half2 l01 = __halves2half2(__float2half_rn(v.x - __half2float(hx)),
                                             __float2half_rn(v.y - __half2float(hy)));
                __half2 l23 = __halves2half2(__float2half_rn(v.z - __half2float(hz)),
                                             __float2half_rn(v.w - __half2float(hw)));
                const uint32_t off = (uint32_t)(row * PITCH + c4) * 2;
                *(__half2*)(smem + SM_YH + off) = h01;
                *(__half2*)(smem + SM_YH + off + 4) = h23;
                *(__half2*)(smem + SM_YL + off) = l01;
                *(__half2*)(smem + SM_YL + off + 4) = l23;
            }
        }
        __syncthreads();

        // GEMM1: L[n=128, bp=64] = (Yh+Yl) * XT^T
        float acc[8][4];
        #pragma unroll
        for (int j = 0; j < 8; j++)
            #pragma unroll
            for (int q = 0; q < 4; q++) acc[j][q] = 0.f;

        const uint32_t aAddr = sb + SM_YH + (uint32_t)(nb + (lane & 15)) * (PITCH * 2)
                             + (uint32_t)(((lane >> 4) << 3) * 2);
        const uint32_t bAddr = sb + SM_XT + (uint32_t)(lane & 7) * (PITCH * 2)
                             + (uint32_t)((((lane >> 3) & 1) << 3) * 2);
        #pragma unroll
        for (int ks = 0; ks < 8; ks++) {
            const uint32_t kOff = (uint32_t)(ks * 32);
            uint32_t ah[4], alr[4];
            ldsm4(aAddr + kOff, ah);
            ldsm4(aAddr + (SM_YL - SM_YH) + kOff, alr);
            #pragma unroll
            for (int j = 0; j < 8; j++) {
                uint32_t bb[2];
                ldsm2(bAddr + (uint32_t)(j * 8) * (PITCH * 2) + kOff, bb);
                mma16816(acc[j], ah, bb);
                mma16816(acc[j], alr, bb);
            }
        }

        // epilogue 1: logits, running max, rescale, exp, running sum
        const int n0 = nb + (lane >> 2);
        const float y20 = *(const float*)(smem + SM_Y2 + n0 * 4);
        const float y21 = *(const float*)(smem + SM_Y2 + (n0 + 8) * 4);
        const float* sAs = (const float*)(smem + SM_SA);
        const float* sCs = (const float*)(smem + SM_SC);

        float lv[4][4];
        float mx[4][2];
        #pragma unroll
        for (int j = 0; j < 4; j++) {
            #pragma unroll
            for (int cc = 0; cc < 2; cc++) {
                const int b2 = j * 8 + 2 * (lane & 3) + cc;
                lv[j][cc]     = acc[j][cc]     + acc[j + 4][cc]     + sAs[b2] - sCs[b2] * y20;
                lv[j][cc + 2] = acc[j][cc + 2] + acc[j + 4][cc + 2] + sAs[b2] - sCs[b2] * y21;
                float m = fmaxf(lv[j][cc], lv[j][cc + 2]);
                #pragma unroll
                for (int o = 4; o < 32; o <<= 1) m = fmaxf(m, __shfl_xor_sync(0xffffffffu, m, o));
                mx[j][cc] = m;
            }
        }
        if (lane < 4) {
            #pragma unroll
            for (int j = 0; j < 4; j++)
                #pragma unroll
                for (int cc = 0; cc < 2; cc++)
                    red[w * 32 + j * 8 + 2 * lane + cc] = mx[j][cc];
        }
        __syncthreads();
        if (t < 32) {
            float m1 = -3.4e38f;
            #pragma unroll
            for (int w2 = 0; w2 < 8; w2++) m1 = fmaxf(m1, red[w2 * 32 + t]);
            const float mo = cmv[t];
            const float mn = fmaxf(mo, m1);
            sfo[t] = ex2f((mo - mn) * L2E);
            cmv[t] = mn;
        }
        __syncthreads();

        // rescale persistent a2 by exp(m_old - m_new) for its two b rows
        {
            const float f0 = sfo[r0 & 31];
            const float f1 = sfo[(r0 + 8) & 31];
            #pragma unroll
            for (int j = 0; j < 8; j++) {
                a2[j][0] *= f0; a2[j][1] *= f0;
                a2[j][2] *= f1; a2[j][3] *= f1;
            }
        }

        float sv[4][2];
        #pragma unroll
        for (int j = 0; j < 4; j++) {
            #pragma unroll
            for (int cc = 0; cc < 2; cc++) {
                const int b2 = j * 8 + 2 * (lane & 3) + cc;
                const float cmb = cmv[b2];
                float e0 = ex2f((lv[j][cc] - cmb) * L2E);
                float e1 = ex2f((lv[j][cc + 2] - cmb) * L2E);
                __half h0 = __float2half_rn(e0), h1 = __float2half_rn(e1);
                __half l0 = __float2half_rn(e0 - __half2float(h0));
                __half l1 = __float2half_rn(e1 - __half2float(h1));
                *(__half*)(smem + SM_ES + ((uint32_t)b2 * PITCH + n0) * 2) = h0;
                *(__half*)(smem + SM_ES + ((uint32_t)b2 * PITCH + n0 + 8) * 2) = h1;
                *(__half*)(smem + SM_ES + ((uint32_t)(b2 + 32) * PITCH + n0) * 2) = l0;
                *(__half*)(smem + SM_ES + ((uint32_t)(b2 + 32) * PITCH + n0 + 8) * 2) = l1;
                float ss = e0 + e1;
                #pragma unroll
                for (int o = 4; o < 32; o <<= 1) ss += __shfl_xor_sync(0xffffffffu, ss, o);
                sv[j][cc] = ss;
            }
        }
        if (lane < 4) {
            #pragma unroll
            for (int j = 0; j < 4; j++)
                #pragma unroll
                for (int cc = 0; cc < 2; cc++)
                    red[w * 32 + j * 8 + 2 * lane + cc] = sv[j][cc];
        }
        __syncthreads();
        if (t < 32) {
            float s1 = 0.f;
            #pragma unroll
            for (int w2 = 0; w2 < 8; w2++) s1 += red[w2 * 32 + t];
            srun[t] = srun[t] * sfo[t] + s1;
        }

        // GEMM2: a2 += ES * (Yh+Yl)
        const uint32_t aeAddr = sb + SM_ES + (uint32_t)(mb + (lane & 15)) * (PITCH * 2)
                              + (uint32_t)(((lane >> 4) << 3) * 2);
        const uint32_t btRow = (uint32_t)(lane & 15) * (PITCH * 2);
        #pragma unroll
        for (int ks = 0; ks < 8; ks++) {
            const uint32_t nOff = (uint32_t)(ks * 16);
            uint32_t ae[4];
            ldsm4(aeAddr + nOff * 2, ae);
            const uint32_t ybase = nOff * (PITCH * 2) + btRow;
            #pragma unroll
            for (int j = 0; j < 8; j++) {
                const uint32_t dOff = (uint32_t)(db + j * 8) * 2;
                uint32_t bh[2], bl[2];
                ldsm2t(sb + SM_YH + ybase + dOff, bh);
                ldsm2t(sb + SM_YL + ybase + dOff, bl);
                mma16816(a2[j], ae, bh);
                mma16816(a2[j], ae, bl);
            }
        }
    }
    __syncthreads();

    // write chunk stats
    if (t < 32) {
        g_cmax[t * NCH + c] = cmv[t];
        g_csum[t * NCH + c] = srun[t];
    }

    // stage a2 -> PS (aliases Y tiles), combine ph+pl, store g_cvec[c][b][d]
    #pragma unroll
    for (int j = 0; j < 8; j++) {
        const int dc = db + j * 8 + 2 * (lane & 3);
        *(float2*)(smem + SM_PS + ((uint32_t)r0 * PITCHF + dc) * 4) =
            make_float2(a2[j][0], a2[j][1]);
        *(float2*)(smem + SM_PS + ((uint32_t)(r0 + 8) * PITCHF + dc) * 4) =
            make_float2(a2[j][2], a2[j][3]);
    }
    __syncthreads();
    #pragma unroll
    for (int i4 = t; i4 < 1024; i4 += NT) {
        const int b2 = i4 >> 5, d4 = (i4 & 31) * 4;
        float4 pa = *(const float4*)(smem + SM_PS + ((uint32_t)b2 * PITCHF + d4) * 4);
        float4 pb = *(const float4*)(smem + SM_PS + ((uint32_t)(b2 + 32) * PITCHF + d4) * 4);
        float4 o = make_float4(pa.x + pb.x, pa.y + pb.y, pa.z + pb.z, pa.w + pb.w);
        *(float4*)(g_cvec + ((size_t)c * B + b2) * D + d4) = o;
    }
}

// ---------------------------------------------------------------------------
// K2: finisher. Grid = B*4 = 128 CTAs, 256 threads. 128 chunks now.
// ---------------------------------------------------------------------------
__global__ __launch_bounds__(256) void k_final(const float* __restrict__ x,
                                               const float* __restrict__ al,
                                               float* __restrict__ out) {
    __shared__ float sc[NCH];
    __shared__ float red[4];
    __shared__ float ps[8][32];
    __shared__ float sM, sSE;
    const int t = threadIdx.x, lane = t & 31, w = t >> 5;
    const int b = blockIdx.x >> 2;
    const int dg = blockIdx.x & 3;

    float cm0 = 0.f;
    if (t < NCH) {
        cm0 = g_cmax[b * NCH + t];
        float m = cm0;
        #pragma unroll
        for (int o = 16; o > 0; o >>= 1) m = fmaxf(m, __shfl_xor_sync(0xffffffffu, m, o));
        if (lane == 0) red[w] = m;
    }
    __syncthreads();
    if (t == 0) sM = fmaxf(fmaxf(red[0], red[1]), fmaxf(red[2], red[3]));
    __syncthreads();
    if (t < NCH) {
        float s = __expf(cm0 - sM);
        sc[t] = s;
        float p = s * g_csum[b * NCH + t];
        #pragma unroll
        for (int o = 16; o > 0; o >>= 1) p += __shfl_xor_sync(0xffffffffu, p, o);
        if (lane == 0) red[w] = p;
    }
    __syncthreads();
    if (t == 0) sSE = red[0] + red[1] + red[2] + red[3];
    __syncthreads();

    // v reduction: warp w -> 16 chunks, lane -> d = dg*32 + lane
    const int d = dg * 32 + lane;
    const float* base = g_cvec + (size_t)b * D + d;
    float v = 0.f;
    #pragma unroll
    for (int jo = 0; jo < 2; jo++) {
        float tmp[8], scv[8];
        #pragma unroll
        for (int ji = 0; ji < 8; ji++) {
            const int cc = w * 16 + jo * 8 + ji;
            tmp[ji] = base[(size_t)cc * B * D];
            scv[ji] = sc[cc];
        }
        #pragma unroll
        for (int ji = 0; ji < 8; ji++) v = fmaf(scv[ji], tmp[ji], v);
    }
    ps[w][lane] = v;
    __syncthreads();

    if (t < 32) {
        float vv = 0.f;
        #pragma unroll
        for (int w2 = 0; w2 < 8; w2++) vv += ps[w2][t];
        const int dd = dg * 32 + t;
        float a = al[b];
        float var = 1.f - a;
        out[b * D + dd] = (x[b * D + dd] - sqrtf(a) * (vv / sSE)) * rsqrtf(var);
    }
}

extern "C" void kernel_launch(void* const* d_in, const int* in_sizes, int n_in,
                              void* d_out, int out_size) {
    const float* x  = (const float*)d_in[0];
    const float* al = (const float*)d_in[1];
    const float* y  = (const float*)d_in[2];
    float* out = (float*)d_out;

    cudaFuncSetAttribute(k_chunk, cudaFuncAttributeMaxDynamicSharedMemorySize, SMEM_TOTAL);

    k_chunk<<<NCH, NT, SMEM_TOTAL>>>(x, al, y);
    k_final<<<B * 4, 256>>>(x, al, out);
}